// round 7
// baseline (speedup 1.0000x reference)
#include <cuda_runtime.h>
#include <math.h>

#define B_DIM 256
#define N_DIM 256
#define D_DIM 512
#define MARGIN 0.5f
#define EPS_V 1e-6f
#define ROWS (B_DIM * N_DIM)           // 65536
#define BND ((size_t)ROWS * D_DIM)     // 33554432

// ---- scratch (device globals; no allocation allowed) ----
__device__ float g_dp[ROWS];
__device__ float g_dn[ROWS];
__device__ float g_loss_partial[B_DIM];
__device__ int   g_neg_idx[B_DIM];
__device__ int   g_pos_idx[B_DIM];
__device__ int   g_valid_neg[B_DIM];
__device__ int   g_valid_pos[B_DIM];
__device__ int   g_perm[2][B_DIM];   // batch visit order, sorted by source idx

// ============================================================
// Kernel 1: per-row L2 distances. Warp-per-row, streaming loads.
// ============================================================
__global__ __launch_bounds__(256) void dist_kernel(
    const float* __restrict__ anchor,
    const float* __restrict__ positive,
    const float* __restrict__ negative)
{
    const int row  = blockIdx.x * 8 + (threadIdx.x >> 5);
    const int lane = threadIdx.x & 31;

    const float4* a4 = (const float4*)(anchor   + (size_t)row * D_DIM);
    const float4* p4 = (const float4*)(positive + (size_t)row * D_DIM);
    const float4* n4 = (const float4*)(negative + (size_t)row * D_DIM);

    float4 av[4], pv[4], nv[4];
    #pragma unroll
    for (int i = 0; i < 4; i++) av[i] = __ldcs(&a4[lane + 32 * i]);
    #pragma unroll
    for (int i = 0; i < 4; i++) pv[i] = __ldcs(&p4[lane + 32 * i]);
    #pragma unroll
    for (int i = 0; i < 4; i++) nv[i] = __ldcs(&n4[lane + 32 * i]);

    float dp = 0.0f, dn = 0.0f;
    #pragma unroll
    for (int i = 0; i < 4; i++) {
        float x0 = av[i].x - pv[i].x + EPS_V, x1 = av[i].y - pv[i].y + EPS_V;
        float x2 = av[i].z - pv[i].z + EPS_V, x3 = av[i].w - pv[i].w + EPS_V;
        dp += x0*x0 + x1*x1 + x2*x2 + x3*x3;
        float y0 = av[i].x - nv[i].x + EPS_V, y1 = av[i].y - nv[i].y + EPS_V;
        float y2 = av[i].z - nv[i].z + EPS_V, y3 = av[i].w - nv[i].w + EPS_V;
        dn += y0*y0 + y1*y1 + y2*y2 + y3*y3;
    }

    #pragma unroll
    for (int off = 16; off > 0; off >>= 1) {
        dp += __shfl_xor_sync(0xFFFFFFFFu, dp, off);
        dn += __shfl_xor_sync(0xFFFFFFFFu, dn, off);
    }

    if (lane == 0) {
        g_dp[row] = sqrtf(dp);
        g_dn[row] = sqrtf(dn);
    }
}

// ============================================================
// Kernel 2: per-batch hard mining + loss partials + valid flags.
// ============================================================
__global__ __launch_bounds__(256) void mine_kernel(float* __restrict__ out)
{
    const int b = blockIdx.x;
    const int n = threadIdx.x;

    const float dp = g_dp[b * N_DIM + n];
    const float dn = g_dn[b * N_DIM + n];

    const bool mask_neg = (dp - dn + MARGIN) > 0.0f;
    const bool mask_pos = (dn - dp + MARGIN) > 0.0f;

    __shared__ float s_sn[N_DIM]; __shared__ int s_in[N_DIM];
    __shared__ float s_sp[N_DIM]; __shared__ int s_ip[N_DIM];
    __shared__ float s_l [N_DIM];

    s_sn[n] = mask_neg ? dn : -INFINITY;  s_in[n] = n;
    s_sp[n] = mask_pos ? dp :  INFINITY;  s_ip[n] = n;
    s_l [n] = fmaxf(0.0f, MARGIN + dp - dn);
    __syncthreads();

    for (int off = N_DIM / 2; off > 0; off >>= 1) {
        if (n < off) {
            float so = s_sn[n + off]; int io = s_in[n + off];
            if (so > s_sn[n] || (so == s_sn[n] && io < s_in[n])) {
                s_sn[n] = so; s_in[n] = io;
            }
            float qo = s_sp[n + off]; int jo = s_ip[n + off];
            if (qo < s_sp[n] || (qo == s_sp[n] && jo < s_ip[n])) {
                s_sp[n] = qo; s_ip[n] = jo;
            }
            s_l[n] += s_l[n + off];
        }
        __syncthreads();
    }

    if (n == 0) {
        const int vn = (s_sn[0] > -INFINITY) ? 1 : 0;
        const int vp = (s_sp[0] <  INFINITY) ? 1 : 0;
        g_neg_idx[b] = s_in[0];
        g_pos_idx[b] = s_ip[0];
        g_valid_neg[b] = vn;
        g_valid_pos[b] = vp;
        g_loss_partial[b] = s_l[0];
        out[1 + 2 * BND + b]         = (float)vn;
        out[1 + 2 * BND + B_DIM + b] = (float)vp;
    }
}

// ============================================================
// Kernel 3: deterministic loss finalize (single block).
// ============================================================
__global__ __launch_bounds__(256) void loss_kernel(float* __restrict__ out)
{
    const int t = threadIdx.x;
    __shared__ float s[B_DIM];
    s[t] = g_loss_partial[t];
    __syncthreads();
    for (int off = B_DIM / 2; off > 0; off >>= 1) {
        if (t < off) s[t] += s[t + off];
        __syncthreads();
    }
    if (t == 0) out[0] = s[0] * (1.0f / (float)(B_DIM * N_DIM));
}

// ============================================================
// Kernel 4: build batch visit order, stably sorted by source index
// (valid batches first, invalid at the end). Atomic-free, fully
// deterministic: each thread computes its own rank with an O(B) scan.
// ============================================================
__global__ __launch_bounds__(256) void perm_kernel()
{
    const int side = blockIdx.x;        // 0 = neg, 1 = pos
    const int t = threadIdx.x;

    const int* idx = (side == 0) ? g_neg_idx   : g_pos_idx;
    const int* val = (side == 0) ? g_valid_neg : g_valid_pos;

    __shared__ int s_idx[B_DIM];
    __shared__ int s_val[B_DIM];
    s_idx[t] = idx[t];
    s_val[t] = val[t];
    __syncthreads();

    const int my  = s_idx[t];
    const int v   = s_val[t];
    int rank = 0;
    if (v) {
        for (int b = 0; b < B_DIM; b++) {
            const int kb = s_idx[b];
            if (s_val[b] && (kb < my || (kb == my && b < t))) rank++;
        }
    } else {
        int nvalid = 0, before = 0;
        for (int b = 0; b < B_DIM; b++) {
            if (s_val[b]) nvalid++;
            else if (b < t) before++;
        }
        rank = nvalid + before;
    }
    g_perm[side][rank] = t;
}

// ============================================================
// Kernel 5: gather with source-sorted scheduling.
// Block = (batch-position, n, side); dest batch = g_perm[side][pos].
// Concurrent blocks share source rows -> duplicate reads hit L2.
// Dest base out+1 is 4B-misaligned: thread t<127 writes elements
// 3+4t..6+4t (16B-aligned -> STG.128); thread 127 writes 0,1,2,511.
// Source reads are scalar (src+3 only 4B-aligned).
// ============================================================
__global__ __launch_bounds__(128) void gather_kernel(
    const float* __restrict__ positive,
    const float* __restrict__ negative,
    float* __restrict__ out)
{
    const int pos  = blockIdx.x;
    const int n    = blockIdx.y;
    const int side = blockIdx.z;
    const int t    = threadIdx.x;

    const int b = g_perm[side][pos];
    const int valid = (side == 0) ? g_valid_neg[b] : g_valid_pos[b];
    const int sidx  = (side == 0) ? g_neg_idx[b]   : g_pos_idx[b];

    const float* __restrict__ src =
        ((side == 0) ? negative : positive) + ((size_t)sidx * N_DIM + n) * D_DIM;
    float* __restrict__ dst =
        out + 1 + (side ? BND : 0) + ((size_t)b * N_DIM + n) * D_DIM;

    if (t < 127) {
        const int e = 3 + 4 * t;
        float4 v = make_float4(0.f, 0.f, 0.f, 0.f);
        if (valid) {
            v.x = __ldg(&src[e + 0]); v.y = __ldg(&src[e + 1]);
            v.z = __ldg(&src[e + 2]); v.w = __ldg(&src[e + 3]);
        }
        __stcs((float4*)(dst + e), v);
    } else {
        float h0 = 0.f, h1 = 0.f, h2 = 0.f, tl = 0.f;
        if (valid) {
            h0 = __ldg(&src[0]); h1 = __ldg(&src[1]);
            h2 = __ldg(&src[2]); tl = __ldg(&src[511]);
        }
        dst[0] = h0; dst[1] = h1; dst[2] = h2; dst[511] = tl;
    }
}

// ============================================================
extern "C" void kernel_launch(void* const* d_in, const int* in_sizes, int n_in,
                              void* d_out, int out_size)
{
    const float* anchor   = (const float*)d_in[0];
    const float* positive = (const float*)d_in[1];
    const float* negative = (const float*)d_in[2];
    float* out = (float*)d_out;

    dist_kernel<<<ROWS / 8, 256>>>(anchor, positive, negative);
    mine_kernel<<<B_DIM, 256>>>(out);
    loss_kernel<<<1, 256>>>(out);
    perm_kernel<<<2, 256>>>();

    dim3 ggrid(B_DIM, N_DIM, 2);
    gather_kernel<<<ggrid, 128>>>(positive, negative, out);
}

// round 8
// speedup vs baseline: 1.0542x; 1.0542x over previous
#include <cuda_runtime.h>
#include <math.h>

#define B_DIM 256
#define N_DIM 256
#define D_DIM 512
#define MARGIN 0.5f
#define EPS_V 1e-6f
#define ROWS (B_DIM * N_DIM)           // 65536
#define BND ((size_t)ROWS * D_DIM)     // 33554432

// ---- scratch (device globals; no allocation allowed) ----
__device__ float g_dp[ROWS];
__device__ float g_dn[ROWS];
__device__ float g_loss_partial[B_DIM];
__device__ int   g_neg_idx[B_DIM];
__device__ int   g_pos_idx[B_DIM];
__device__ int   g_valid_neg[B_DIM];
__device__ int   g_valid_pos[B_DIM];
__device__ int   g_perm[2][B_DIM];   // batch visit order, sorted by source idx

// ============================================================
// Kernel 1: per-row L2 distances. Warp-per-row, streaming loads.
// ============================================================
__global__ __launch_bounds__(256) void dist_kernel(
    const float* __restrict__ anchor,
    const float* __restrict__ positive,
    const float* __restrict__ negative)
{
    const int row  = blockIdx.x * 8 + (threadIdx.x >> 5);
    const int lane = threadIdx.x & 31;

    const float4* a4 = (const float4*)(anchor   + (size_t)row * D_DIM);
    const float4* p4 = (const float4*)(positive + (size_t)row * D_DIM);
    const float4* n4 = (const float4*)(negative + (size_t)row * D_DIM);

    float4 av[4], pv[4], nv[4];
    #pragma unroll
    for (int i = 0; i < 4; i++) av[i] = __ldcs(&a4[lane + 32 * i]);
    #pragma unroll
    for (int i = 0; i < 4; i++) pv[i] = __ldcs(&p4[lane + 32 * i]);
    #pragma unroll
    for (int i = 0; i < 4; i++) nv[i] = __ldcs(&n4[lane + 32 * i]);

    float dp = 0.0f, dn = 0.0f;
    #pragma unroll
    for (int i = 0; i < 4; i++) {
        float x0 = av[i].x - pv[i].x + EPS_V, x1 = av[i].y - pv[i].y + EPS_V;
        float x2 = av[i].z - pv[i].z + EPS_V, x3 = av[i].w - pv[i].w + EPS_V;
        dp += x0*x0 + x1*x1 + x2*x2 + x3*x3;
        float y0 = av[i].x - nv[i].x + EPS_V, y1 = av[i].y - nv[i].y + EPS_V;
        float y2 = av[i].z - nv[i].z + EPS_V, y3 = av[i].w - nv[i].w + EPS_V;
        dn += y0*y0 + y1*y1 + y2*y2 + y3*y3;
    }

    #pragma unroll
    for (int off = 16; off > 0; off >>= 1) {
        dp += __shfl_xor_sync(0xFFFFFFFFu, dp, off);
        dn += __shfl_xor_sync(0xFFFFFFFFu, dn, off);
    }

    if (lane == 0) {
        g_dp[row] = sqrtf(dp);
        g_dn[row] = sqrtf(dn);
    }
}

// ============================================================
// Kernel 2: per-batch hard mining + loss partials + valid flags.
// ============================================================
__global__ __launch_bounds__(256) void mine_kernel(float* __restrict__ out)
{
    const int b = blockIdx.x;
    const int n = threadIdx.x;

    const float dp = g_dp[b * N_DIM + n];
    const float dn = g_dn[b * N_DIM + n];

    const bool mask_neg = (dp - dn + MARGIN) > 0.0f;
    const bool mask_pos = (dn - dp + MARGIN) > 0.0f;

    __shared__ float s_sn[N_DIM]; __shared__ int s_in[N_DIM];
    __shared__ float s_sp[N_DIM]; __shared__ int s_ip[N_DIM];
    __shared__ float s_l [N_DIM];

    s_sn[n] = mask_neg ? dn : -INFINITY;  s_in[n] = n;
    s_sp[n] = mask_pos ? dp :  INFINITY;  s_ip[n] = n;
    s_l [n] = fmaxf(0.0f, MARGIN + dp - dn);
    __syncthreads();

    for (int off = N_DIM / 2; off > 0; off >>= 1) {
        if (n < off) {
            float so = s_sn[n + off]; int io = s_in[n + off];
            if (so > s_sn[n] || (so == s_sn[n] && io < s_in[n])) {
                s_sn[n] = so; s_in[n] = io;
            }
            float qo = s_sp[n + off]; int jo = s_ip[n + off];
            if (qo < s_sp[n] || (qo == s_sp[n] && jo < s_ip[n])) {
                s_sp[n] = qo; s_ip[n] = jo;
            }
            s_l[n] += s_l[n + off];
        }
        __syncthreads();
    }

    if (n == 0) {
        const int vn = (s_sn[0] > -INFINITY) ? 1 : 0;
        const int vp = (s_sp[0] <  INFINITY) ? 1 : 0;
        g_neg_idx[b] = s_in[0];
        g_pos_idx[b] = s_ip[0];
        g_valid_neg[b] = vn;
        g_valid_pos[b] = vp;
        g_loss_partial[b] = s_l[0];
        out[1 + 2 * BND + b]         = (float)vn;
        out[1 + 2 * BND + B_DIM + b] = (float)vp;
    }
}

// ============================================================
// Kernel 3: finalize. Block 0: loss sum + perm for side 0.
// Block 1: perm for side 1.
// perm = stable counting sort of batches by source index (valid first,
// invalid appended in batch order). Valid placement uses per-bin atomics
// (order within a bin is scheduling-only; output bytes unaffected).
// ============================================================
__global__ __launch_bounds__(256) void finalize_kernel(float* __restrict__ out)
{
    const int side = blockIdx.x;        // 0 = neg, 1 = pos
    const int t = threadIdx.x;

    // ---- loss (block 0 only) ----
    __shared__ float s_l[B_DIM];
    if (side == 0) {
        s_l[t] = g_loss_partial[t];
        __syncthreads();
        for (int off = B_DIM / 2; off > 0; off >>= 1) {
            if (t < off) s_l[t] += s_l[t + off];
            __syncthreads();
        }
        if (t == 0) out[0] = s_l[0] * (1.0f / (float)(B_DIM * N_DIM));
    }

    // ---- perm via counting sort ----
    const int* idx = (side == 0) ? g_neg_idx   : g_pos_idx;
    const int* val = (side == 0) ? g_valid_neg : g_valid_pos;

    __shared__ int s_cnt[B_DIM];
    __shared__ int s_a[B_DIM];
    __shared__ int s_b[B_DIM];
    __shared__ int s_cur[B_DIM];
    __shared__ int s_nvalid;

    const int my_idx = idx[t];
    const int my_val = val[t];

    s_cnt[t] = 0;
    __syncthreads();
    if (my_val) atomicAdd(&s_cnt[my_idx], 1);
    __syncthreads();

    // prefix sum #1: histogram -> bin offsets (double-buffered inclusive)
    {
        const int v = s_cnt[t];
        s_a[t] = v;
        __syncthreads();
        int* cur = s_a; int* nxt = s_b;
        for (int d = 1; d < B_DIM; d <<= 1) {
            nxt[t] = (t >= d) ? (cur[t] + cur[t - d]) : cur[t];
            __syncthreads();
            int* tmp = cur; cur = nxt; nxt = tmp;
        }
        s_cur[t] = cur[t] - v;           // exclusive bin offset
        if (t == B_DIM - 1) s_nvalid = cur[t];
        __syncthreads();
    }

    if (my_val) {
        int p = atomicAdd(&s_cur[my_idx], 1);
        g_perm[side][p] = t;
    }
    __syncthreads();

    // prefix sum #2: invalid placement, atomic-free and stable
    {
        const int inv = my_val ? 0 : 1;
        s_a[t] = inv;
        __syncthreads();
        int* cur = s_a; int* nxt = s_b;
        for (int d = 1; d < B_DIM; d <<= 1) {
            nxt[t] = (t >= d) ? (cur[t] + cur[t - d]) : cur[t];
            __syncthreads();
            int* tmp = cur; cur = nxt; nxt = tmp;
        }
        if (inv) g_perm[side][s_nvalid + cur[t] - 1] = t;
    }
}

// ============================================================
// Kernel 4: gather with source-sorted scheduling.
// Block = (batch-position, n, side); dest batch = g_perm[side][pos].
// Concurrent blocks share source rows -> duplicate reads hit L2.
// Dest base out+1 is 4B-misaligned: thread t<127 writes elements
// 3+4t..6+4t (16B-aligned -> STG.128); thread 127 writes 0,1,2,511.
// Source reads are scalar (src+3 only 4B-aligned).
// ============================================================
__global__ __launch_bounds__(128) void gather_kernel(
    const float* __restrict__ positive,
    const float* __restrict__ negative,
    float* __restrict__ out)
{
    const int pos  = blockIdx.x;
    const int n    = blockIdx.y;
    const int side = blockIdx.z;
    const int t    = threadIdx.x;

    const int b = g_perm[side][pos];
    const int valid = (side == 0) ? g_valid_neg[b] : g_valid_pos[b];
    const int sidx  = (side == 0) ? g_neg_idx[b]   : g_pos_idx[b];

    const float* __restrict__ src =
        ((side == 0) ? negative : positive) + ((size_t)sidx * N_DIM + n) * D_DIM;
    float* __restrict__ dst =
        out + 1 + (side ? BND : 0) + ((size_t)b * N_DIM + n) * D_DIM;

    if (t < 127) {
        const int e = 3 + 4 * t;
        float4 v = make_float4(0.f, 0.f, 0.f, 0.f);
        if (valid) {
            v.x = __ldg(&src[e + 0]); v.y = __ldg(&src[e + 1]);
            v.z = __ldg(&src[e + 2]); v.w = __ldg(&src[e + 3]);
        }
        __stcs((float4*)(dst + e), v);
    } else {
        float h0 = 0.f, h1 = 0.f, h2 = 0.f, tl = 0.f;
        if (valid) {
            h0 = __ldg(&src[0]); h1 = __ldg(&src[1]);
            h2 = __ldg(&src[2]); tl = __ldg(&src[511]);
        }
        dst[0] = h0; dst[1] = h1; dst[2] = h2; dst[511] = tl;
    }
}

// ============================================================
extern "C" void kernel_launch(void* const* d_in, const int* in_sizes, int n_in,
                              void* d_out, int out_size)
{
    const float* anchor   = (const float*)d_in[0];
    const float* positive = (const float*)d_in[1];
    const float* negative = (const float*)d_in[2];
    float* out = (float*)d_out;

    dist_kernel    <<<ROWS / 8, 256>>>(anchor, positive, negative);
    mine_kernel    <<<B_DIM, 256>>>(out);
    finalize_kernel<<<2, 256>>>(out);

    dim3 ggrid(B_DIM, N_DIM, 2);
    gather_kernel<<<ggrid, 128>>>(positive, negative, out);
}

// round 10
// speedup vs baseline: 1.0548x; 1.0006x over previous
#include <cuda_runtime.h>
#include <math.h>

#define B_DIM 256
#define N_DIM 256
#define D_DIM 512
#define MARGIN 0.5f
#define EPS_V 1e-6f
#define ROWS (B_DIM * N_DIM)           // 65536
#define BND ((size_t)ROWS * D_DIM)     // 33554432

// ---- scratch (device globals; no allocation allowed) ----
__device__ float g_dp[ROWS];
__device__ float g_dn[ROWS];
__device__ float g_loss_partial[B_DIM];
__device__ int   g_neg_idx[B_DIM];
__device__ int   g_pos_idx[B_DIM];
__device__ int   g_valid_neg[B_DIM];
__device__ int   g_valid_pos[B_DIM];
__device__ int   g_perm[2][B_DIM];   // batch visit order, sorted by source idx

// ============================================================
// Kernel 1: per-row L2 distances. Warp-per-row, streaming loads.
// ============================================================
__global__ __launch_bounds__(256) void dist_kernel(
    const float* __restrict__ anchor,
    const float* __restrict__ positive,
    const float* __restrict__ negative)
{
    const int row  = blockIdx.x * 8 + (threadIdx.x >> 5);
    const int lane = threadIdx.x & 31;

    const float4* a4 = (const float4*)(anchor   + (size_t)row * D_DIM);
    const float4* p4 = (const float4*)(positive + (size_t)row * D_DIM);
    const float4* n4 = (const float4*)(negative + (size_t)row * D_DIM);

    float4 av[4], pv[4], nv[4];
    #pragma unroll
    for (int i = 0; i < 4; i++) av[i] = __ldcs(&a4[lane + 32 * i]);
    #pragma unroll
    for (int i = 0; i < 4; i++) pv[i] = __ldcs(&p4[lane + 32 * i]);
    #pragma unroll
    for (int i = 0; i < 4; i++) nv[i] = __ldcs(&n4[lane + 32 * i]);

    float dp = 0.0f, dn = 0.0f;
    #pragma unroll
    for (int i = 0; i < 4; i++) {
        float x0 = av[i].x - pv[i].x + EPS_V, x1 = av[i].y - pv[i].y + EPS_V;
        float x2 = av[i].z - pv[i].z + EPS_V, x3 = av[i].w - pv[i].w + EPS_V;
        dp += x0*x0 + x1*x1 + x2*x2 + x3*x3;
        float y0 = av[i].x - nv[i].x + EPS_V, y1 = av[i].y - nv[i].y + EPS_V;
        float y2 = av[i].z - nv[i].z + EPS_V, y3 = av[i].w - nv[i].w + EPS_V;
        dn += y0*y0 + y1*y1 + y2*y2 + y3*y3;
    }

    #pragma unroll
    for (int off = 16; off > 0; off >>= 1) {
        dp += __shfl_xor_sync(0xFFFFFFFFu, dp, off);
        dn += __shfl_xor_sync(0xFFFFFFFFu, dn, off);
    }

    if (lane == 0) {
        g_dp[row] = sqrtf(dp);
        g_dn[row] = sqrtf(dn);
    }
}

// ============================================================
// Kernel 2: per-batch hard mining + loss partials + valid flags.
// ============================================================
__global__ __launch_bounds__(256) void mine_kernel(float* __restrict__ out)
{
    const int b = blockIdx.x;
    const int n = threadIdx.x;

    const float dp = g_dp[b * N_DIM + n];
    const float dn = g_dn[b * N_DIM + n];

    const bool mask_neg = (dp - dn + MARGIN) > 0.0f;
    const bool mask_pos = (dn - dp + MARGIN) > 0.0f;

    __shared__ float s_sn[N_DIM]; __shared__ int s_in[N_DIM];
    __shared__ float s_sp[N_DIM]; __shared__ int s_ip[N_DIM];
    __shared__ float s_l [N_DIM];

    s_sn[n] = mask_neg ? dn : -INFINITY;  s_in[n] = n;
    s_sp[n] = mask_pos ? dp :  INFINITY;  s_ip[n] = n;
    s_l [n] = fmaxf(0.0f, MARGIN + dp - dn);
    __syncthreads();

    for (int off = N_DIM / 2; off > 0; off >>= 1) {
        if (n < off) {
            float so = s_sn[n + off]; int io = s_in[n + off];
            if (so > s_sn[n] || (so == s_sn[n] && io < s_in[n])) {
                s_sn[n] = so; s_in[n] = io;
            }
            float qo = s_sp[n + off]; int jo = s_ip[n + off];
            if (qo < s_sp[n] || (qo == s_sp[n] && jo < s_ip[n])) {
                s_sp[n] = qo; s_ip[n] = jo;
            }
            s_l[n] += s_l[n + off];
        }
        __syncthreads();
    }

    if (n == 0) {
        const int vn = (s_sn[0] > -INFINITY) ? 1 : 0;
        const int vp = (s_sp[0] <  INFINITY) ? 1 : 0;
        g_neg_idx[b] = s_in[0];
        g_pos_idx[b] = s_ip[0];
        g_valid_neg[b] = vn;
        g_valid_pos[b] = vp;
        g_loss_partial[b] = s_l[0];
        out[1 + 2 * BND + b]         = (float)vn;
        out[1 + 2 * BND + B_DIM + b] = (float)vp;
    }
}

// ============================================================
// Kernel 3: finalize. Block 0: loss sum + perm for side 0.
// Block 1: perm for side 1.
// perm = stable counting sort of batches by source index (valid first,
// invalid appended in batch order). Valid placement uses per-bin atomics
// (order within a bin is scheduling-only; output bytes unaffected).
// ============================================================
__global__ __launch_bounds__(256) void finalize_kernel(float* __restrict__ out)
{
    const int side = blockIdx.x;        // 0 = neg, 1 = pos
    const int t = threadIdx.x;

    // ---- loss (block 0 only) ----
    __shared__ float s_l[B_DIM];
    if (side == 0) {
        s_l[t] = g_loss_partial[t];
        __syncthreads();
        for (int off = B_DIM / 2; off > 0; off >>= 1) {
            if (t < off) s_l[t] += s_l[t + off];
            __syncthreads();
        }
        if (t == 0) out[0] = s_l[0] * (1.0f / (float)(B_DIM * N_DIM));
    }

    // ---- perm via counting sort ----
    const int* idx = (side == 0) ? g_neg_idx   : g_pos_idx;
    const int* val = (side == 0) ? g_valid_neg : g_valid_pos;

    __shared__ int s_cnt[B_DIM];
    __shared__ int s_a[B_DIM];
    __shared__ int s_b[B_DIM];
    __shared__ int s_cur[B_DIM];
    __shared__ int s_nvalid;

    const int my_idx = idx[t];
    const int my_val = val[t];

    s_cnt[t] = 0;
    __syncthreads();
    if (my_val) atomicAdd(&s_cnt[my_idx], 1);
    __syncthreads();

    // prefix sum #1: histogram -> bin offsets (double-buffered inclusive)
    {
        const int v = s_cnt[t];
        s_a[t] = v;
        __syncthreads();
        int* cur = s_a; int* nxt = s_b;
        for (int d = 1; d < B_DIM; d <<= 1) {
            nxt[t] = (t >= d) ? (cur[t] + cur[t - d]) : cur[t];
            __syncthreads();
            int* tmp = cur; cur = nxt; nxt = tmp;
        }
        s_cur[t] = cur[t] - v;           // exclusive bin offset
        if (t == B_DIM - 1) s_nvalid = cur[t];
        __syncthreads();
    }

    if (my_val) {
        int p = atomicAdd(&s_cur[my_idx], 1);
        g_perm[side][p] = t;
    }
    __syncthreads();

    // prefix sum #2: invalid placement, atomic-free and stable
    {
        const int inv = my_val ? 0 : 1;
        s_a[t] = inv;
        __syncthreads();
        int* cur = s_a; int* nxt = s_b;
        for (int d = 1; d < B_DIM; d <<= 1) {
            nxt[t] = (t >= d) ? (cur[t] + cur[t - d]) : cur[t];
            __syncthreads();
            int* tmp = cur; cur = nxt; nxt = tmp;
        }
        if (inv) g_perm[side][s_nvalid + cur[t] - 1] = t;
    }
}

// ============================================================
// Kernel 4: gather with source-sorted scheduling.
// Block = (batch-position, n, side); dest batch = g_perm[side][pos].
// Concurrent blocks share source rows -> duplicate reads hit L2.
// Dest base out+1 is 4B-misaligned: thread t<127 writes elements
// 3+4t..6+4t (16B-aligned -> STG.128); thread 127 writes 0,1,2,511.
// Source reads are scalar (src+3 only 4B-aligned).
// ============================================================
__global__ __launch_bounds__(128) void gather_kernel(
    const float* __restrict__ positive,
    const float* __restrict__ negative,
    float* __restrict__ out)
{
    const int pos  = blockIdx.x;
    const int n    = blockIdx.y;
    const int side = blockIdx.z;
    const int t    = threadIdx.x;

    const int b = g_perm[side][pos];
    const int valid = (side == 0) ? g_valid_neg[b] : g_valid_pos[b];
    const int sidx  = (side == 0) ? g_neg_idx[b]   : g_pos_idx[b];

    const float* __restrict__ src =
        ((side == 0) ? negative : positive) + ((size_t)sidx * N_DIM + n) * D_DIM;
    float* __restrict__ dst =
        out + 1 + (side ? BND : 0) + ((size_t)b * N_DIM + n) * D_DIM;

    if (t < 127) {
        const int e = 3 + 4 * t;
        float4 v = make_float4(0.f, 0.f, 0.f, 0.f);
        if (valid) {
            v.x = __ldg(&src[e + 0]); v.y = __ldg(&src[e + 1]);
            v.z = __ldg(&src[e + 2]); v.w = __ldg(&src[e + 3]);
        }
        __stcs((float4*)(dst + e), v);
    } else {
        float h0 = 0.f, h1 = 0.f, h2 = 0.f, tl = 0.f;
        if (valid) {
            h0 = __ldg(&src[0]); h1 = __ldg(&src[1]);
            h2 = __ldg(&src[2]); tl = __ldg(&src[511]);
        }
        dst[0] = h0; dst[1] = h1; dst[2] = h2; dst[511] = tl;
    }
}

// ============================================================
extern "C" void kernel_launch(void* const* d_in, const int* in_sizes, int n_in,
                              void* d_out, int out_size)
{
    const float* anchor   = (const float*)d_in[0];
    const float* positive = (const float*)d_in[1];
    const float* negative = (const float*)d_in[2];
    float* out = (float*)d_out;

    dist_kernel    <<<ROWS / 8, 256>>>(anchor, positive, negative);
    mine_kernel    <<<B_DIM, 256>>>(out);
    finalize_kernel<<<2, 256>>>(out);

    dim3 ggrid(B_DIM, N_DIM, 2);
    gather_kernel<<<ggrid, 128>>>(positive, negative, out);
}